// round 1
// baseline (speedup 1.0000x reference)
#include <cuda_runtime.h>
#include <cuda_bf16.h>

// Problem shape (fixed by setup_inputs): voxels [B, D, H, W] fp32
constexpr int B  = 16;
constexpr int D  = 128;
constexpr int H  = 128;
constexpr int W  = 128;
constexpr int W4 = W / 4;        // float4 groups along W
constexpr int HW4 = H * W4;      // 4096 float4 per depth plane per batch

// out[b, H-1-h, w] = e^EPS * o[0] + sum_{d>=1} (prod_{k<d}(1-o[k])) * o[d]
__global__ void __launch_bounds__(256) ray_term_kernel(
    const float4* __restrict__ vox, float4* __restrict__ out)
{
    const int idx = blockIdx.x * blockDim.x + threadIdx.x;   // 0 .. B*H*W4-1
    const int w4 = idx & (W4 - 1);
    const int h  = (idx / W4) & (H - 1);
    const int b  = idx / HW4;

    const float4* p = vox + (size_t)b * D * HW4 + (size_t)h * W4 + w4;

    const float LO   = 1e-5f;
    const float HIc  = 1.0f - 1e-5f;
    const float EEPS = 1.0000100000500002f;   // exp(1e-5)

    float acc[4], T[4];

    // d = 0 (carries the e^EPS factor from the eps background slab)
    {
        float4 q = __ldg(p);
        float o[4] = {q.x, q.y, q.z, q.w};
        #pragma unroll
        for (int i = 0; i < 4; ++i) {
            float oc = fminf(fmaxf(o[i], LO), HIc);
            acc[i] = EEPS * oc;
            T[i]   = 1.0f - oc;
        }
    }

    // d = 1 .. D-1: running transmittance product, termination prob accumulate
    #pragma unroll 4
    for (int d = 1; d < D; ++d) {
        float4 q = __ldg(p + (size_t)d * HW4);
        float o[4] = {q.x, q.y, q.z, q.w};
        #pragma unroll
        for (int i = 0; i < 4; ++i) {
            float oc = fminf(fmaxf(o[i], LO), HIc);
            acc[i] = fmaf(T[i], oc, acc[i]);
            T[i] *= (1.0f - oc);
        }
    }

    // flip along H on output
    out[(size_t)b * HW4 + (size_t)(H - 1 - h) * W4 + w4] =
        make_float4(acc[0], acc[1], acc[2], acc[3]);
}

extern "C" void kernel_launch(void* const* d_in, const int* in_sizes, int n_in,
                              void* d_out, int out_size)
{
    const float4* vox = (const float4*)d_in[0];
    float4* out = (float4*)d_out;

    const int total = B * HW4;           // 65536 threads
    ray_term_kernel<<<total / 256, 256>>>(vox, out);
}

// round 2
// speedup vs baseline: 1.0104x; 1.0104x over previous
#include <cuda_runtime.h>
#include <cuda_bf16.h>

constexpr int B   = 16;
constexpr int D   = 128;
constexpr int H   = 128;
constexpr int W   = 128;
constexpr int W4  = W / 4;        // 32 float4 per row
constexpr int HW4 = H * W4;       // 4096 float4 per depth plane per batch
constexpr int SEG  = 4;           // depth segments per ray
constexpr int DSEG = D / SEG;     // 32 planes per segment

// out[b, H-1-h, w] = e^EPS * o[0] + sum_{d>=1} (prod_{k<d}(1-o[k])) * o[d]
__global__ void __launch_bounds__(256) ray_term_split_kernel(
    const float4* __restrict__ vox, float4* __restrict__ out)
{
    const int tid  = blockIdx.x * blockDim.x + threadIdx.x;  // 0 .. B*H*W4*SEG-1
    const int lane = tid & 31;
    const int seg  = lane >> 3;          // 0..3
    const int r    = lane & 7;           // ray slot within warp
    const int warp = tid >> 5;           // global warp id, 8 rays each
    const int ray  = warp * 8 + r;       // 0 .. 65535

    const int w4 = ray & (W4 - 1);
    const int h  = (ray / W4) & (H - 1);
    const int b  = ray / HW4;

    const float4* p = vox + (size_t)b * D * HW4
                          + (size_t)(seg * DSEG) * HW4
                          + (size_t)h * W4 + w4;

    const float LO    = 1e-5f;
    const float HIc   = 1.0f - 1e-5f;
    const float EEPSm1 = 1.0000050000166667e-05f;   // exp(1e-5) - 1

    float acc[4] = {0.f, 0.f, 0.f, 0.f};
    float T[4]   = {1.f, 1.f, 1.f, 1.f};
    float oc0[4];

    // uniform segment loop: acc += T*o ; T *= (1-o)
    #pragma unroll 8
    for (int d = 0; d < DSEG; ++d) {
        float4 q = __ldg(p + (size_t)d * HW4);
        float o[4] = {q.x, q.y, q.z, q.w};
        #pragma unroll
        for (int i = 0; i < 4; ++i) {
            float oc = fminf(fmaxf(o[i], LO), HIc);
            if (d == 0) oc0[i] = oc;
            acc[i] = fmaf(T[i], oc, acc[i]);
            T[i] *= (1.0f - oc);
        }
    }

    // seg 0 carries the e^EPS background-slab factor on its first plane
    if (seg == 0) {
        #pragma unroll
        for (int i = 0; i < 4; ++i) acc[i] = fmaf(EEPSm1, oc0[i], acc[i]);
    }

    // compose segments: out = a0 + T0*(a1 + T1*(a2 + T2*a3))
    float fin[4];
    #pragma unroll
    for (int i = 0; i < 4; ++i) {
        float a1 = __shfl_sync(0xFFFFFFFFu, acc[i], r + 8);
        float t1 = __shfl_sync(0xFFFFFFFFu, T[i],   r + 8);
        float a2 = __shfl_sync(0xFFFFFFFFu, acc[i], r + 16);
        float t2 = __shfl_sync(0xFFFFFFFFu, T[i],   r + 16);
        float a3 = __shfl_sync(0xFFFFFFFFu, acc[i], r + 24);
        float v  = fmaf(t2, a3, a2);
        v        = fmaf(t1, v,  a1);
        fin[i]   = fmaf(T[i], v, acc[i]);
    }

    if (seg == 0) {
        out[(size_t)b * HW4 + (size_t)(H - 1 - h) * W4 + w4] =
            make_float4(fin[0], fin[1], fin[2], fin[3]);
    }
}

extern "C" void kernel_launch(void* const* d_in, const int* in_sizes, int n_in,
                              void* d_out, int out_size)
{
    const float4* vox = (const float4*)d_in[0];
    float4* out = (float4*)d_out;

    const int total = B * HW4 * SEG;     // 262144 threads
    ray_term_split_kernel<<<total / 256, 256>>>(vox, out);
}

// round 3
// speedup vs baseline: 1.1355x; 1.1238x over previous
#include <cuda_runtime.h>
#include <cstdint>

constexpr int B = 16, D = 128, H = 128, W = 128;
constexpr int G  = 4;                    // rows per CTA
constexpr int NS = 8;                    // pipeline stages
constexpr int STAGE_FLOATS = G * W;      // 512 floats = 2 KB
constexpr int STAGE_BYTES  = STAGE_FLOATS * 4;
constexpr int THREADS = STAGE_FLOATS / 4;  // 128 threads, one float4 each
constexpr int NCTA = B * H / G;            // 512

__device__ __forceinline__ uint32_t smem_u32(const void* p) {
    return (uint32_t)__cvta_generic_to_shared(p);
}

__device__ __forceinline__ void mbar_wait(uint32_t mb, uint32_t parity) {
    asm volatile(
        "{\n\t"
        ".reg .pred P;\n\t"
        "WL_%=:\n\t"
        "mbarrier.try_wait.parity.acquire.cta.shared::cta.b64 P, [%0], %1, 0x989680;\n\t"
        "@P bra.uni WD_%=;\n\t"
        "bra.uni WL_%=;\n\t"
        "WD_%=:\n\t"
        "}"
        :: "r"(mb), "r"(parity) : "memory");
}

__device__ __forceinline__ void tma_issue(uint32_t dst_smem, const float* src, uint32_t mb) {
    asm volatile(
        "mbarrier.arrive.expect_tx.shared.b64 _, [%0], %1;"
        :: "r"(mb), "r"((uint32_t)STAGE_BYTES) : "memory");
    asm volatile(
        "cp.async.bulk.shared::cluster.global.mbarrier::complete_tx::bytes "
        "[%0], [%1], %2, [%3];"
        :: "r"(dst_smem), "l"(src), "r"((uint32_t)STAGE_BYTES), "r"(mb) : "memory");
}

__global__ void __launch_bounds__(THREADS) ray_term_tma_kernel(
    const float* __restrict__ vox, float* __restrict__ out)
{
    __shared__ __align__(16) float buf[NS][STAGE_FLOATS];
    __shared__ __align__(8)  uint64_t mbar[NS];

    const int tid = threadIdx.x;
    const int cta = blockIdx.x;
    const int b   = cta / (H / G);
    const int h0  = (cta % (H / G)) * G;

    if (tid == 0) {
        #pragma unroll
        for (int s = 0; s < NS; ++s)
            asm volatile("mbarrier.init.shared.b64 [%0], 1;"
                         :: "r"(smem_u32(&mbar[s])) : "memory");
        asm volatile("fence.proxy.async.shared::cta;" ::: "memory");
    }
    __syncthreads();

    // source base for this CTA's 4-row strip; +d*H*W per depth plane
    const float* src_base = vox + ((size_t)b * D * H + h0) * W;

    // prologue: fill all stages
    if (tid == 0) {
        #pragma unroll
        for (int s = 0; s < NS; ++s)
            tma_issue(smem_u32(&buf[s][0]), src_base + (size_t)s * H * W,
                      smem_u32(&mbar[s]));
    }

    const float LO     = 1e-5f;
    const float HIc    = 1.0f - 1e-5f;
    const float EEPSm1 = 1.0000050000166667e-05f;   // exp(1e-5) - 1

    float acc[4] = {0.f, 0.f, 0.f, 0.f};
    float T[4]   = {1.f, 1.f, 1.f, 1.f};
    float oc0[4] = {0.f, 0.f, 0.f, 0.f};

    int parity = 0;
    for (int db = 0; db < D; db += NS) {
        #pragma unroll
        for (int s = 0; s < NS; ++s) {
            const int d = db + s;
            mbar_wait(smem_u32(&mbar[s]), (uint32_t)parity);

            float4 q = *(const float4*)&buf[s][tid * 4];
            float o[4] = {q.x, q.y, q.z, q.w};
            #pragma unroll
            for (int i = 0; i < 4; ++i) {
                float oc = fminf(fmaxf(o[i], LO), HIc);
                if (d == 0) oc0[i] = oc;
                acc[i] = fmaf(T[i], oc, acc[i]);
                T[i] *= (1.0f - oc);
            }

            __syncthreads();   // all lanes done with stage s -> safe to refill

            if (tid == 0 && d + NS < D)
                tma_issue(smem_u32(&buf[s][0]), src_base + (size_t)(d + NS) * H * W,
                          smem_u32(&mbar[s]));
        }
        parity ^= 1;
    }

    // background-slab factor e^EPS applies to the d=0 term
    #pragma unroll
    for (int i = 0; i < 4; ++i) acc[i] = fmaf(EEPSm1, oc0[i], acc[i]);

    // output with vertical flip: thread owns row h0 + (tid>>5), cols (tid&31)*4
    const int rl = tid >> 5;          // 0..3
    const int w4 = tid & 31;
    const int h  = h0 + rl;
    ((float4*)out)[(size_t)b * H * (W / 4) + (size_t)(H - 1 - h) * (W / 4) + w4] =
        make_float4(acc[0], acc[1], acc[2], acc[3]);
}

extern "C" void kernel_launch(void* const* d_in, const int* in_sizes, int n_in,
                              void* d_out, int out_size)
{
    const float* vox = (const float*)d_in[0];
    float* out = (float*)d_out;
    ray_term_tma_kernel<<<NCTA, THREADS>>>(vox, out);
}

// round 4
// speedup vs baseline: 1.2273x; 1.0808x over previous
#include <cuda_runtime.h>
#include <cstdint>

constexpr int B = 16, D = 128, H = 128, W = 128;
constexpr int HW = H * W;
constexpr int G  = 4;                       // rows per CTA
constexpr int PS = 2;                       // depth planes per pipeline stage
constexpr int NS = 8;                       // pipeline stages
constexpr int PLANE_FLOATS = G * W;         // 512 floats = 2 KB per plane-strip
constexpr int PLANE_BYTES  = PLANE_FLOATS * 4;
constexpr int STAGE_FLOATS = PLANE_FLOATS * PS;   // 1024 floats = 4 KB
constexpr int THREADS = PLANE_FLOATS / 4;   // 128 threads
constexpr int NCTA = B * H / G;             // 512
constexpr int NT = D / PS;                  // 64 stage-consumptions per CTA

__device__ __forceinline__ uint32_t smem_u32(const void* p) {
    return (uint32_t)__cvta_generic_to_shared(p);
}

__device__ __forceinline__ void mbar_wait(uint32_t mb, uint32_t parity) {
    asm volatile(
        "{\n\t"
        ".reg .pred P;\n\t"
        "WL_%=:\n\t"
        "mbarrier.try_wait.parity.acquire.cta.shared::cta.b64 P, [%0], %1, 0x989680;\n\t"
        "@P bra.uni WD_%=;\n\t"
        "bra.uni WL_%=;\n\t"
        "WD_%=:\n\t"
        "}"
        :: "r"(mb), "r"(parity) : "memory");
}

// one stage = 2 bulk copies (planes d, d+1) + one expect_tx for both
__device__ __forceinline__ void tma_issue_pair(uint32_t dst_smem, const float* src, uint32_t mb) {
    asm volatile(
        "mbarrier.arrive.expect_tx.shared.b64 _, [%0], %1;"
        :: "r"(mb), "r"((uint32_t)(PS * PLANE_BYTES)) : "memory");
    asm volatile(
        "cp.async.bulk.shared::cluster.global.mbarrier::complete_tx::bytes "
        "[%0], [%1], %2, [%3];"
        :: "r"(dst_smem), "l"(src), "r"((uint32_t)PLANE_BYTES), "r"(mb) : "memory");
    asm volatile(
        "cp.async.bulk.shared::cluster.global.mbarrier::complete_tx::bytes "
        "[%0], [%1], %2, [%3];"
        :: "r"(dst_smem + PLANE_BYTES), "l"(src + HW), "r"((uint32_t)PLANE_BYTES), "r"(mb)
        : "memory");
}

__global__ void __launch_bounds__(THREADS) ray_term_tma2_kernel(
    const float* __restrict__ vox, float* __restrict__ out)
{
    __shared__ __align__(16) float buf[NS][STAGE_FLOATS];
    __shared__ __align__(8)  uint64_t mbar[NS];

    const int tid = threadIdx.x;
    const int cta = blockIdx.x;
    const int b   = cta / (H / G);
    const int h0  = (cta % (H / G)) * G;

    if (tid == 0) {
        #pragma unroll
        for (int s = 0; s < NS; ++s)
            asm volatile("mbarrier.init.shared.b64 [%0], 1;"
                         :: "r"(smem_u32(&mbar[s])) : "memory");
        asm volatile("fence.proxy.async.shared::cta;" ::: "memory");
    }
    __syncthreads();

    const float* src_base = vox + ((size_t)b * D * H + h0) * W;

    // prologue: 8 threads each fill one stage (planes 2s, 2s+1)
    if (tid < NS)
        tma_issue_pair(smem_u32(&buf[tid][0]),
                       src_base + (size_t)(tid * PS) * HW,
                       smem_u32(&mbar[tid]));

    const float LO     = 1e-5f;
    const float HIc    = 1.0f - 1e-5f;
    const float EEPSm1 = 1.0000050000166667e-05f;   // exp(1e-5) - 1

    float acc[4] = {0.f, 0.f, 0.f, 0.f};
    float T[4]   = {1.f, 1.f, 1.f, 1.f};
    float oc0[4] = {0.f, 0.f, 0.f, 0.f};

    int parity = 0;
    for (int tb = 0; tb < NT; tb += NS) {
        #pragma unroll
        for (int s = 0; s < NS; ++s) {
            const int t = tb + s;                 // stage-consumption index
            mbar_wait(smem_u32(&mbar[s]), (uint32_t)parity);

            float4 q0 = *(const float4*)&buf[s][tid * 4];
            float4 q1 = *(const float4*)&buf[s][PLANE_FLOATS + tid * 4];

            float oA[4] = {q0.x, q0.y, q0.z, q0.w};
            float oB[4] = {q1.x, q1.y, q1.z, q1.w};
            #pragma unroll
            for (int i = 0; i < 4; ++i) {
                float ocA = fminf(fmaxf(oA[i], LO), HIc);
                if (t == 0) oc0[i] = ocA;
                acc[i] = fmaf(T[i], ocA, acc[i]);
                T[i] *= (1.0f - ocA);
                float ocB = fminf(fmaxf(oB[i], LO), HIc);
                acc[i] = fmaf(T[i], ocB, acc[i]);
                T[i] *= (1.0f - ocB);
            }

            __syncthreads();   // everyone done with stage s -> safe to refill

            if (t + NS < NT && tid == ((s & 3) << 5))
                tma_issue_pair(smem_u32(&buf[s][0]),
                               src_base + (size_t)((t + NS) * PS) * HW,
                               smem_u32(&mbar[s]));
        }
        parity ^= 1;
    }

    // background-slab factor e^EPS applies to the d=0 term
    #pragma unroll
    for (int i = 0; i < 4; ++i) acc[i] = fmaf(EEPSm1, oc0[i], acc[i]);

    // output with vertical flip
    const int rl = tid >> 5;
    const int w4 = tid & 31;
    const int h  = h0 + rl;
    ((float4*)out)[(size_t)b * H * (W / 4) + (size_t)(H - 1 - h) * (W / 4) + w4] =
        make_float4(acc[0], acc[1], acc[2], acc[3]);
}

extern "C" void kernel_launch(void* const* d_in, const int* in_sizes, int n_in,
                              void* d_out, int out_size)
{
    const float* vox = (const float*)d_in[0];
    float* out = (float*)d_out;
    ray_term_tma2_kernel<<<NCTA, THREADS>>>(vox, out);
}